// round 3
// baseline (speedup 1.0000x reference)
#include <cuda_runtime.h>

// Shapes fixed by problem: N=1024 nodes, D=256 feat, H=256 hidden.
#define NN 1024
#define DD 256
#define HH 256
#define NBLK 128          // <= 148 SMs, 1 CTA/SM -> all co-resident -> device barrier safe
#define NTHR 512          // 16 warps/block for latency hiding

// Scratch (__device__ globals: allocation-free rule)
__device__ float g_p[DD];     // w1[:D] @ w2
__device__ float g_q[DD];     // w1[D:] @ w2
__device__ float g_c;         // b1.w2 + b2
__device__ float g_eu[NN];    // exp(-(u_i + c))
__device__ float g_ev[NN];    // exp(-v_i)

__device__ unsigned g_bar_count = 0;   // resets to 0 each crossing
__device__ unsigned g_bar_gen   = 0;   // monotonically increments (wrap-safe)

__device__ __forceinline__ float warp_reduce(float v) {
#pragma unroll
    for (int o = 16; o > 0; o >>= 1) v += __shfl_xor_sync(0xffffffffu, v, o);
    return v;
}

__device__ __forceinline__ float frcp(float x) {
    float y;
    asm("rcp.approx.f32 %0, %1;" : "=f"(y) : "f"(x));
    return y;
}

// Sense-reversing grid barrier (all NBLK CTAs co-resident).
__device__ __forceinline__ void grid_barrier() {
    __syncthreads();
    if (threadIdx.x == 0) {
        __threadfence();
        unsigned gen = *(volatile unsigned*)&g_bar_gen;
        unsigned t = atomicAdd(&g_bar_count, 1u);
        if (t == NBLK - 1) {
            g_bar_count = 0;
            __threadfence();
            atomicAdd(&g_bar_gen, 1u);   // release
        } else {
            while (*(volatile unsigned*)&g_bar_gen == gen) { }
        }
        __threadfence();
    }
    __syncthreads();
}

__global__ void __launch_bounds__(NTHR, 1)
fused_decoder(const float* __restrict__ z,  const float* __restrict__ w1,
              const float* __restrict__ b1, const float* __restrict__ w2,
              const float* __restrict__ b2, float* __restrict__ out) {
    const int lane  = threadIdx.x & 31;
    const int wid   = threadIdx.x >> 5;                       // 0..15
    const int gwarp = blockIdx.x * (NTHR / 32) + wid;         // 0..2047

    // ---- Phase A: p = w1_top@w2, q = w1_bot@w2, c = b1.w2 + b2 ----
    // One warp per w1 row; 2x float4 per thread (256 floats / 32 lanes).
    if (gwarp < 2 * DD) {
        const float4* row = reinterpret_cast<const float4*>(w1 + (size_t)gwarp * HH);
        const float4* w2v = reinterpret_cast<const float4*>(w2);
        float4 r0 = row[lane];
        float4 r1 = row[lane + 32];
        float4 a0 = w2v[lane];
        float4 a1 = w2v[lane + 32];
        float acc = r0.x * a0.x;
        acc = fmaf(r0.y, a0.y, acc);
        acc = fmaf(r0.z, a0.z, acc);
        acc = fmaf(r0.w, a0.w, acc);
        acc = fmaf(r1.x, a1.x, acc);
        acc = fmaf(r1.y, a1.y, acc);
        acc = fmaf(r1.z, a1.z, acc);
        acc = fmaf(r1.w, a1.w, acc);
        acc = warp_reduce(acc);
        if (lane == 0) {
            if (gwarp < DD) g_p[gwarp] = acc;
            else            g_q[gwarp - DD] = acc;
        }
    } else if (gwarp == 2 * DD) {
        const float4* b1v = reinterpret_cast<const float4*>(b1);
        const float4* w2v = reinterpret_cast<const float4*>(w2);
        float4 r0 = b1v[lane];
        float4 r1 = b1v[lane + 32];
        float4 a0 = w2v[lane];
        float4 a1 = w2v[lane + 32];
        float acc = r0.x * a0.x;
        acc = fmaf(r0.y, a0.y, acc);
        acc = fmaf(r0.z, a0.z, acc);
        acc = fmaf(r0.w, a0.w, acc);
        acc = fmaf(r1.x, a1.x, acc);
        acc = fmaf(r1.y, a1.y, acc);
        acc = fmaf(r1.z, a1.z, acc);
        acc = fmaf(r1.w, a1.w, acc);
        acc = warp_reduce(acc);
        if (lane == 0) g_c = acc + b2[0];
    }

    grid_barrier();

    // ---- Phase B: eu_i = exp(-(z_i.p + c)), ev_i = exp(-(z_i.q)) ----
    // One warp per node row (warps 0..1023), 2x float4 per thread.
    if (gwarp < NN) {
        const float4* row = reinterpret_cast<const float4*>(z + (size_t)gwarp * DD);
        const float4* pv  = reinterpret_cast<const float4*>(g_p);
        const float4* qv  = reinterpret_cast<const float4*>(g_q);
        float4 z0 = row[lane];
        float4 z1 = row[lane + 32];
        float4 p0 = pv[lane];
        float4 p1 = pv[lane + 32];
        float4 q0 = qv[lane];
        float4 q1 = qv[lane + 32];
        float su = z0.x * p0.x;
        su = fmaf(z0.y, p0.y, su);
        su = fmaf(z0.z, p0.z, su);
        su = fmaf(z0.w, p0.w, su);
        su = fmaf(z1.x, p1.x, su);
        su = fmaf(z1.y, p1.y, su);
        su = fmaf(z1.z, p1.z, su);
        su = fmaf(z1.w, p1.w, su);
        float sv = z0.x * q0.x;
        sv = fmaf(z0.y, q0.y, sv);
        sv = fmaf(z0.z, q0.z, sv);
        sv = fmaf(z0.w, q0.w, sv);
        sv = fmaf(z1.x, q1.x, sv);
        sv = fmaf(z1.y, q1.y, sv);
        sv = fmaf(z1.z, q1.z, sv);
        sv = fmaf(z1.w, q1.w, sv);
        su = warp_reduce(su);
        sv = warp_reduce(sv);
        if (lane == 0) {
            g_eu[gwarp] = __expf(-(su + g_c));
            g_ev[gwarp] = __expf(-sv);
        }
    }

    grid_barrier();

    // ---- Phase C: adj[i,j] = 0.5*(1/(1+eu_i*ev_j) + 1/(1+eu_j*ev_i)) ----
    // Block covers 8 rows; 512 threads process 2 rows per sweep (256 cols each as float4).
    const int colg    = threadIdx.x & 255;      // float4 column group 0..255
    const int row_sub = threadIdx.x >> 8;       // 0..1
    const int j = colg * 4;
    const float4 euj = *reinterpret_cast<const float4*>(g_eu + j);
    const float4 evj = *reinterpret_cast<const float4*>(g_ev + j);
#pragma unroll
    for (int rr = 0; rr < 4; rr++) {
        const int i = blockIdx.x * 8 + rr * 2 + row_sub;
        const float eui = g_eu[i];
        const float evi = g_ev[i];
        float4 o;
        o.x = 0.5f * (frcp(fmaf(eui, evj.x, 1.f)) + frcp(fmaf(euj.x, evi, 1.f)));
        o.y = 0.5f * (frcp(fmaf(eui, evj.y, 1.f)) + frcp(fmaf(euj.y, evi, 1.f)));
        o.z = 0.5f * (frcp(fmaf(eui, evj.z, 1.f)) + frcp(fmaf(euj.z, evi, 1.f)));
        o.w = 0.5f * (frcp(fmaf(eui, evj.w, 1.f)) + frcp(fmaf(euj.w, evi, 1.f)));
        reinterpret_cast<float4*>(out)[(size_t)i * (NN / 4) + colg] = o;
    }
}

extern "C" void kernel_launch(void* const* d_in, const int* in_sizes, int n_in,
                              void* d_out, int out_size) {
    const float* z  = (const float*)d_in[0];  // [N, D]
    const float* w1 = (const float*)d_in[1];  // [2D, H]
    const float* b1 = (const float*)d_in[2];  // [H]
    const float* w2 = (const float*)d_in[3];  // [H]
    const float* b2 = (const float*)d_in[4];  // [1]
    float* out = (float*)d_out;               // [N, N]

    fused_decoder<<<NBLK, NTHR>>>(z, w1, b1, w2, b2, out);
}